// round 10
// baseline (speedup 1.0000x reference)
#include <cuda_runtime.h>

#define FULL 0xffffffffu

constexpr int B = 4096;
constexpr int K = 64;
constexpr int L = 128;
constexpr int E_DIM = 16;

__device__ float g_loss[B];
__device__ unsigned g_ctr = 0;

// Wavefront-pipelined pHMM forward with FLOWING INITIALIZATION:
// Two batch elements per warp (16-lane halves). Lane h owns states
// {4h..4h+3}; lane 15 shadows state 64. At wall-iteration w lane h processes
// step l = w - h, consuming lane h-1's same-step exports (v3 = fM'[4h],
// fd4 = fD'[4h]) produced at iteration w-1.
//
// No ramp guards anywhere: the all-zero state is an exact fixpoint of the
// step update (zero imports -> zero exports), and the init delete-chain
// fDinit[k] = Add[k-1]*fDinit[k-1] has the same dataflow as a regular step
// with fM = 0. Lane 0 is preset (fM[0]=1, own fD chain, exports
// (v3=0, fd4=fDinit[4])); every other lane starts at exact zero and the
// wavefront constructs its init at w = h-1. After a lane's step 127 its
// junk exports are consumed only by downstream junk steps (skew property),
// and only lane 15's final state is read.
//
// Per-lane power-of-2 exponent Ex; alignment factor af = 2^(E_{h-1}-E_h) is
// piecewise-constant between rescale heads ((w & 3) == 3) and refreshed only
// there; af = 0 on lane 0 absorbs the k=0 boundary. Idle (all-zero) lanes
// force exv = 0 so rescale is a no-op for them.
// Export shortcut: fd4 = segB*fd0 + (c0*u0 + c1*u1 + c2*u2 + u3) keeps the
// import->export serial chain at one FMA. Transitions order:
// M2M,M2I,M2D,I2M,I2I,D2M,D2D.

#define ITER(WV, RESC) do {                                                    \
    float pv3 = __shfl_up_sync(FULL, v3x, 1, 16);                              \
    float pfd = __shfl_up_sync(FULL, fd4x, 1, 16);                             \
    float4 ev = *(const float4*)(epbh + nsymB);  /* conflict-free LDS.128 */   \
    nsymB = rawp[WV];                         /* prefetch next step (x<<8) */  \
    float pv3a = pv3 * af;                                                     \
    float pfda = pfd * af;                                                     \
    float q0 = fmaf(Amm0, FM0, fmaf(Aim0, FI0, Adm0 * FD0));                   \
    float q1 = fmaf(Amm1, FM1, fmaf(Aim1, FI1, Adm1 * FD1));                   \
    float q2 = fmaf(Amm2, FM2, fmaf(Aim2, FI2, Adm2 * FD2));                   \
    float q3 = fmaf(Amm3, FM3, fmaf(Aim3, FI3, Adm3 * FD3));                   \
    float nI0 = fmaf(AqMI0, FM0, AqII0 * FI0);                                 \
    float nI1 = fmaf(AqMI1, FM1, AqII1 * FI1);                                 \
    float nI2 = fmaf(AqMI2, FM2, AqII2 * FI2);                                 \
    float nI3 = fmaf(AqMI3, FM3, AqII3 * FI3);                                 \
    float nFI64 = fmaf(Aq64MI, v3x, Aq64II * FI64);                            \
    float v0 = ev.x * q0, v1 = ev.y * q1, v2 = ev.z * q2, nv3 = ev.w * q3;     \
    float u0 = Amd0 * pv3a, u1 = Amd1 * v0, u2 = Amd2 * v1, u3 = Amd3 * v2;    \
    float t1 = fmaf(c2, u2, u3);                                               \
    float t2 = fmaf(c1, u1, t1);                                               \
    float alpha = fmaf(c0, u0, t2);                                            \
    float fd0 = pfda;                                                          \
    float nfd4 = fmaf(segB, fd0, alpha);     /* export: 1 FMA off import */    \
    float fd1 = fmaf(Add0, fd0, u0);                                           \
    float fd2 = fmaf(Add1, fd1, u1);                                           \
    float fd3 = fmaf(Add2, fd2, u2);                                           \
    float nM0 = pv3a, nM1 = v0, nM2 = v1, nM3 = v2;                            \
    int exv = 0;                                                               \
    if (RESC) {                                                                \
        float m = fmaxf(fmaxf(nM0, nM1), fmaxf(nM2, nM3));                     \
        m = fmaxf(m, fmaxf(fmaxf(nI0, nI1), fmaxf(nI2, nI3)));                 \
        m = fmaxf(m, fmaxf(fmaxf(fd0, fd1), fmaxf(fd2, fd3)));                 \
        m = fmaxf(m, fmaxf(nv3, fmaxf(nfd4, nFI64)));                          \
        exv = (int)((__float_as_uint(m) >> 23) & 255) - 127;                   \
        exv = (m > 0.0f) ? exv : 0;          /* idle lanes: no-op rescale */   \
        float sc = __uint_as_float((unsigned)(127 - exv) << 23);               \
        nM0 *= sc; nM1 *= sc; nM2 *= sc; nM3 *= sc;                            \
        nI0 *= sc; nI1 *= sc; nI2 *= sc; nI3 *= sc;                            \
        fd0 *= sc; fd1 *= sc; fd2 *= sc; fd3 *= sc;                            \
        nv3 *= sc; nfd4 *= sc; nFI64 *= sc;                                    \
    }                                                                          \
    FM0 = nM0; FM1 = nM1; FM2 = nM2; FM3 = nM3;                                \
    FI0 = nI0; FI1 = nI1; FI2 = nI2; FI3 = nI3;                                \
    FD0 = fd0; FD1 = fd1; FD2 = fd2; FD3 = fd3;                                \
    FI64 = nFI64; v3x = nv3; fd4x = nfd4; Ex += exv;                           \
    if (RESC) {   /* refresh alignment factor (valid until next head) */       \
        int pE = __shfl_up_sync(FULL, Ex, 1, 16);                              \
        int dE = pE - Ex; dE = max(-126, min(126, dE));                        \
        af = (h == 0) ? 0.0f                                                   \
                      : __uint_as_float((unsigned)(127 + dE) << 23);           \
    }                                                                          \
} while (0)

__global__ __launch_bounds__(64) void phmm_kernel(
    const int*   __restrict__ x,
    const float* __restrict__ a,
    const float* __restrict__ e,
    const float* __restrict__ mus,
    const float* __restrict__ lvs,
    float*       __restrict__ out)
{
    const int lane = threadIdx.x & 31;
    const int half = lane >> 4;
    const int h    = lane & 15;
    const int wIn  = threadIdx.x >> 5;
    const int warp = blockIdx.x * 2 + wIn;
    const int b = 2 * warp + half;

    __shared__ float4 sh_e[2 * 2 * 4 * 16];  // [warp][half][symbol][hlane]
    __shared__ int    sh_x[2 * 2 * 160];     // padded symbols (×256 pre-scaled)
    __shared__ float sw[2];
    __shared__ unsigned s_rank;

    const float* ab = a + (size_t)b * (K + 1) * 7;
    const int k0 = 4 * h;
    const float* A0 = ab + (k0 + 0) * 7;
    const float* A1 = ab + (k0 + 1) * 7;
    const float* A2 = ab + (k0 + 2) * 7;
    const float* A3 = ab + (k0 + 3) * 7;

    float Amm0 = __expf(A0[0]), Amm1 = __expf(A1[0]);
    float Amm2 = __expf(A2[0]), Amm3 = __expf(A3[0]);
    float AqMI0 = 0.25f * __expf(A0[1]), AqMI1 = 0.25f * __expf(A1[1]);
    float AqMI2 = 0.25f * __expf(A2[1]), AqMI3 = 0.25f * __expf(A3[1]);
    float Amd0 = __expf(A0[2]), Amd1 = __expf(A1[2]);
    float Amd2 = __expf(A2[2]), Amd3 = __expf(A3[2]);
    float Aim0 = __expf(A0[3]), Aim1 = __expf(A1[3]);
    float Aim2 = __expf(A2[3]), Aim3 = __expf(A3[3]);
    float AqII0 = 0.25f * __expf(A0[4]), AqII1 = 0.25f * __expf(A1[4]);
    float AqII2 = 0.25f * __expf(A2[4]), AqII3 = 0.25f * __expf(A3[4]);
    float Adm0 = __expf(A0[5]), Adm1 = __expf(A1[5]);
    float Adm2 = __expf(A2[5]), Adm3 = __expf(A3[5]);
    float Add0 = __expf(A0[6]), Add1 = __expf(A1[6]);
    float Add2 = __expf(A2[6]), Add3 = __expf(A3[6]);

    // Export/alpha coefficients: fd4 = segB*fd0 + c0*u0 + c1*u1 + c2*u2 + u3
    float c2 = Add3;
    float c1 = Add3 * Add2;
    float c0 = c1 * Add1;
    float segB = c0 * Add0;

    const float* a64 = ab + K * 7;
    float A64mm  = __expf(a64[0]);
    float Aq64MI = 0.25f * __expf(a64[1]);
    float A64im  = __expf(a64[3]);
    float Aq64II = 0.25f * __expf(a64[4]);
    float A64dm  = __expf(a64[5]);

    // Emission LUT (conflict-free LDS.128): epb[sym*16+h] = exp(e[4h..4h+3][sym])
    const float4* e4 = (const float4*)(e + (size_t)b * K * 4);
    float4 e0 = e4[k0], e1 = e4[k0 + 1], e2 = e4[k0 + 2], e3 = e4[k0 + 3];
    float4* epb = sh_e + (size_t)((wIn * 2 + half) * 4) * 16;
    epb[0 * 16 + h] = make_float4(__expf(e0.x), __expf(e1.x), __expf(e2.x), __expf(e3.x));
    epb[1 * 16 + h] = make_float4(__expf(e0.y), __expf(e1.y), __expf(e2.y), __expf(e3.y));
    epb[2 * 16 + h] = make_float4(__expf(e0.z), __expf(e1.z), __expf(e2.z), __expf(e3.z));
    epb[3 * 16 + h] = make_float4(__expf(e0.w), __expf(e1.w), __expf(e2.w), __expf(e3.w));
    const char* epbh = (const char*)epb + h * 16;

    // Symbols to shared, pre-scaled by 256 (LUT byte offset), padded 16
    // front/back so the skewed prefetch never clamps.
    const int4* x4 = (const int4*)(x + (size_t)b * L);
    int* xr = sh_x + (wIn * 2 + half) * 160;
    {
        int4 xa = x4[h], xb = x4[h + 16];
        xr[h] = 0; xr[144 + h] = 0;
        xr[16 + 4 * h + 0] = xa.x << 8;
        xr[16 + 4 * h + 1] = xa.y << 8;
        xr[16 + 4 * h + 2] = xa.z << 8;
        xr[16 + 4 * h + 3] = xa.w << 8;
        xr[80 + 4 * h + 0] = xb.x << 8;
        xr[80 + 4 * h + 1] = xb.y << 8;
        xr[80 + 4 * h + 2] = xb.z << 8;
        xr[80 + 4 * h + 3] = xb.w << 8;
    }
    const int* rawp = xr + 17 - h;   // rawp[w] = x[w - h + 1] << 8

    // Flowing init: lane 0 preset; all other lanes exactly zero.
    float FM0 = (h == 0) ? 1.0f : 0.0f;
    float FM1 = 0.0f, FM2 = 0.0f, FM3 = 0.0f;
    float FI0 = 0.0f, FI1 = 0.0f, FI2 = 0.0f, FI3 = 0.0f;
    float FI64 = 0.0f;
    float v3x = 0.0f;                 // export fM'[4h+4] / fM[64] shadow
    float FD0 = 0.0f, FD1 = 0.0f, FD2 = 0.0f, FD3 = 0.0f;
    float fd4x = 0.0f;                // export fD'[4h+4] / fD[64] shadow
    if (h == 0) {
        FD1 = Amd0;                   // fDinit[1] = Amd[0] * fM0[0]
        FD2 = Add1 * FD1;             // fDinit[2]
        FD3 = Add2 * FD2;             // fDinit[3]
        fd4x = Add3 * FD3;            // export fDinit[4] for lane 1's init step
    }
    int Ex = 0;
    float af = (h == 0) ? 0.0f : 1.0f;

    __syncthreads();                  // shared LUTs + symbols visible

    int nsymB = (h == 0) ? xr[16] : 0;   // symbol for lane's w=0 step (pad for h>0)

    // ── uniform, guard-free loop: w = 0..142; rescale heads at w ≡ 3 (mod 4)
    ITER(0, false);
    ITER(1, false);
    ITER(2, false);
    #pragma unroll 1
    for (int wb = 3; wb < 143; wb += 4) {
        ITER(wb,     true);
        ITER(wb + 1, false);
        ITER(wb + 2, false);
        ITER(wb + 3, false);
    }

    // KLD: each hlane handles one latent dim for its batch.
    float kt;
    {
        float mu = mus[(size_t)b * E_DIM + h];
        float lv = lvs[(size_t)b * E_DIM + h];
        kt = 1.0f + lv - mu * mu - __expf(lv);
    }
    kt += __shfl_xor_sync(FULL, kt, 8, 16);
    kt += __shfl_xor_sync(FULL, kt, 4, 16);
    kt += __shfl_xor_sync(FULL, kt, 2, 16);
    kt += __shfl_xor_sync(FULL, kt, 1, 16);
    float kld = -0.5f * kt;

    if (h == 15) {
        // Lane 15's step 127 committed on the last iteration (w = 142):
        // fM[64]=v3x, fI[64]=FI64, fD[64]=fd4x at scale 2^Ex.
        float fin = fmaf(A64mm, v3x, fmaf(A64im, FI64, A64dm * fd4x));
        g_loss[b] = -(logf(fin) + (float)Ex * 0.69314718055994531f) + kld;
    }

    // ── Fused deterministic final reduction (last-block-done) ──
    __threadfence();
    __syncthreads();
    if (threadIdx.x == 0) s_rank = atomicAdd(&g_ctr, 1);
    __syncthreads();
    if (s_rank == gridDim.x - 1) {
        __threadfence();
        float v = 0.0f;
        #pragma unroll
        for (int i = 0; i < B / 64; ++i)
            v += __ldcg(&g_loss[threadIdx.x + i * 64]);
        v += __shfl_xor_sync(FULL, v, 16);
        v += __shfl_xor_sync(FULL, v, 8);
        v += __shfl_xor_sync(FULL, v, 4);
        v += __shfl_xor_sync(FULL, v, 2);
        v += __shfl_xor_sync(FULL, v, 1);
        if (lane == 0) sw[wIn] = v;
        __syncthreads();
        if (threadIdx.x == 0) {
            out[0] = (sw[0] + sw[1]) * (1.0f / (float)B);
            g_ctr = 0;   // reset for next graph replay
        }
    }
}

extern "C" void kernel_launch(void* const* d_in, const int* in_sizes, int n_in,
                              void* d_out, int out_size)
{
    const int*   x   = (const int*)d_in[0];
    const float* a   = (const float*)d_in[1];
    const float* e   = (const float*)d_in[2];
    const float* mus = (const float*)d_in[3];
    const float* lvs = (const float*)d_in[4];

    // 1024 blocks × 2 warps × 2 batches/warp = 4096 batch elements.
    phmm_kernel<<<B / 4, 64>>>(x, a, e, mus, lvs, (float*)d_out);
}

// round 13
// speedup vs baseline: 1.0141x; 1.0141x over previous
#include <cuda_runtime.h>

#define FULL 0xffffffffu

constexpr int B = 4096;
constexpr int K = 64;
constexpr int L = 128;
constexpr int E_DIM = 16;

__device__ float g_loss[B];
__device__ unsigned g_ctr = 0;

// Wavefront-pipelined pHMM forward with flowing initialization.
// Two batch elements per warp (16-lane halves). Lane h owns states
// {4h..4h+3}; lane 15 shadows state 64. At wall-iteration w lane h processes
// step l = w - h, consuming lane h-1's same-step exports (v3 = fM'[4h],
// fd4 = fD'[4h]) produced at iteration w-1. No ramp guards: all-zero state
// is an exact fixpoint; lane 0 is preset and the wavefront constructs each
// lane's init in flight.
//
// SI fold: insert state is stored pre-multiplied, SI_k = Aim_k * fI_k, so
// q_k = Amm*FM + Adm*FD + SI (2 fma, no mul). SI update:
// SI'_k = P_k*FM_k + AqII_k*SI_k with P_k = Aim_k * 0.25 * exp(M2I),
// AqII_k = 0.25 * exp(I2I). State 64: SI64 = A64im * fI64; the final sum
// uses SI64 directly.
//
// Per-lane power-of-2 exponent Ex; alignment factor af = 2^(E_{h-1}-E_h) is
// piecewise-constant between rescale heads ((w & 3) == 3), refreshed there;
// af = 0 on lane 0 absorbs the k=0 boundary.
// The rescale max MUST include the SI values: SI has a self-loop
// (AqII can be > 1) whose growth is not bounded by the fM mass — keying the
// rescale to fM alone lets SI overflow (R11 failure). Full set: nM, nI, fd,
// nv3, nfd4, nSI64. Idle (all-zero) lanes force exv = 0.
// Export shortcut: fd4 = segB*fd0 + (c0*u0 + c1*u1 + c2*u2 + u3).
// Transitions order: M2M,M2I,M2D,I2M,I2I,D2M,D2D.

#define ITER(WV, RESC) do {                                                    \
    float pv3 = __shfl_up_sync(FULL, v3x, 1, 16);                              \
    float pfd = __shfl_up_sync(FULL, fd4x, 1, 16);                             \
    float4 ev = *(const float4*)(epbh + nsymB);  /* conflict-free LDS.128 */   \
    nsymB = rawp[WV];                         /* prefetch next step (x<<8) */  \
    float pv3a = pv3 * af;                                                     \
    float pfda = pfd * af;                                                     \
    float q0 = fmaf(Amm0, FM0, fmaf(Adm0, FD0, SI0));                          \
    float q1 = fmaf(Amm1, FM1, fmaf(Adm1, FD1, SI1));                          \
    float q2 = fmaf(Amm2, FM2, fmaf(Adm2, FD2, SI2));                          \
    float q3 = fmaf(Amm3, FM3, fmaf(Adm3, FD3, SI3));                          \
    float nI0 = fmaf(P0, FM0, AqII0 * SI0);                                    \
    float nI1 = fmaf(P1, FM1, AqII1 * SI1);                                    \
    float nI2 = fmaf(P2, FM2, AqII2 * SI2);                                    \
    float nI3 = fmaf(P3, FM3, AqII3 * SI3);                                    \
    float nSI64 = fmaf(P64, v3x, Aq64II * SI64);                               \
    float v0 = ev.x * q0, v1 = ev.y * q1, v2 = ev.z * q2, nv3 = ev.w * q3;     \
    float u0 = Amd0 * pv3a, u1 = Amd1 * v0, u2 = Amd2 * v1, u3 = Amd3 * v2;    \
    float t1 = fmaf(c2, u2, u3);                                               \
    float t2 = fmaf(c1, u1, t1);                                               \
    float alpha = fmaf(c0, u0, t2);                                            \
    float fd0 = pfda;                                                          \
    float nfd4 = fmaf(segB, fd0, alpha);     /* export: 1 FMA off import */    \
    float fd1 = fmaf(Add0, fd0, u0);                                           \
    float fd2 = fmaf(Add1, fd1, u1);                                           \
    float fd3 = fmaf(Add2, fd2, u2);                                           \
    float nM0 = pv3a, nM1 = v0, nM2 = v1, nM3 = v2;                            \
    int exv = 0;                                                               \
    if (RESC) {                                                                \
        float m = fmaxf(fmaxf(nM0, nM1), fmaxf(nM2, nM3));                     \
        m = fmaxf(m, fmaxf(fmaxf(nI0, nI1), fmaxf(nI2, nI3)));                 \
        m = fmaxf(m, fmaxf(fmaxf(fd0, fd1), fmaxf(fd2, fd3)));                 \
        m = fmaxf(m, fmaxf(nv3, fmaxf(nfd4, nSI64)));                          \
        exv = (int)((__float_as_uint(m) >> 23) & 255) - 127;                   \
        exv = (m > 0.0f) ? exv : 0;          /* idle lanes: no-op rescale */   \
        float sc = __uint_as_float((unsigned)(127 - exv) << 23);               \
        nM0 *= sc; nM1 *= sc; nM2 *= sc; nM3 *= sc;                            \
        nI0 *= sc; nI1 *= sc; nI2 *= sc; nI3 *= sc;                            \
        fd0 *= sc; fd1 *= sc; fd2 *= sc; fd3 *= sc;                            \
        nv3 *= sc; nfd4 *= sc; nSI64 *= sc;                                    \
    }                                                                          \
    FM0 = nM0; FM1 = nM1; FM2 = nM2; FM3 = nM3;                                \
    SI0 = nI0; SI1 = nI1; SI2 = nI2; SI3 = nI3;                                \
    FD0 = fd0; FD1 = fd1; FD2 = fd2; FD3 = fd3;                                \
    SI64 = nSI64; v3x = nv3; fd4x = nfd4; Ex += exv;                           \
    if (RESC) {   /* refresh alignment factor (valid until next head) */       \
        int pE = __shfl_up_sync(FULL, Ex, 1, 16);                              \
        int dE = pE - Ex; dE = max(-126, min(126, dE));                        \
        af = (h == 0) ? 0.0f                                                   \
                      : __uint_as_float((unsigned)(127 + dE) << 23);           \
    }                                                                          \
} while (0)

__global__ __launch_bounds__(64) void phmm_kernel(
    const int*   __restrict__ x,
    const float* __restrict__ a,
    const float* __restrict__ e,
    const float* __restrict__ mus,
    const float* __restrict__ lvs,
    float*       __restrict__ out)
{
    const int lane = threadIdx.x & 31;
    const int half = lane >> 4;
    const int h    = lane & 15;
    const int wIn  = threadIdx.x >> 5;
    const int warp = blockIdx.x * 2 + wIn;
    const int b = 2 * warp + half;

    __shared__ float4 sh_e[2 * 2 * 4 * 16];  // [warp][half][symbol][hlane]
    __shared__ int    sh_x[2 * 2 * 160];     // padded symbols (×256 pre-scaled)
    __shared__ float sw[2];
    __shared__ unsigned s_rank;

    const float* ab = a + (size_t)b * (K + 1) * 7;
    const int k0 = 4 * h;
    const float* A0 = ab + (k0 + 0) * 7;
    const float* A1 = ab + (k0 + 1) * 7;
    const float* A2 = ab + (k0 + 2) * 7;
    const float* A3 = ab + (k0 + 3) * 7;

    float Amm0 = __expf(A0[0]), Amm1 = __expf(A1[0]);
    float Amm2 = __expf(A2[0]), Amm3 = __expf(A3[0]);
    float Amd0 = __expf(A0[2]), Amd1 = __expf(A1[2]);
    float Amd2 = __expf(A2[2]), Amd3 = __expf(A3[2]);
    float Aim0 = __expf(A0[3]), Aim1 = __expf(A1[3]);
    float Aim2 = __expf(A2[3]), Aim3 = __expf(A3[3]);
    // SI-fold coefficients: P = Aim * (0.25 * exp(M2I)), AqII = 0.25 * exp(I2I)
    float P0 = Aim0 * 0.25f * __expf(A0[1]), P1 = Aim1 * 0.25f * __expf(A1[1]);
    float P2 = Aim2 * 0.25f * __expf(A2[1]), P3 = Aim3 * 0.25f * __expf(A3[1]);
    float AqII0 = 0.25f * __expf(A0[4]), AqII1 = 0.25f * __expf(A1[4]);
    float AqII2 = 0.25f * __expf(A2[4]), AqII3 = 0.25f * __expf(A3[4]);
    float Adm0 = __expf(A0[5]), Adm1 = __expf(A1[5]);
    float Adm2 = __expf(A2[5]), Adm3 = __expf(A3[5]);
    float Add0 = __expf(A0[6]), Add1 = __expf(A1[6]);
    float Add2 = __expf(A2[6]), Add3 = __expf(A3[6]);

    // Export/alpha coefficients: fd4 = segB*fd0 + c0*u0 + c1*u1 + c2*u2 + u3
    float c2 = Add3;
    float c1 = Add3 * Add2;
    float c0 = c1 * Add1;
    float segB = c0 * Add0;

    const float* a64 = ab + K * 7;
    float A64mm  = __expf(a64[0]);
    float A64im  = __expf(a64[3]);
    float P64    = A64im * 0.25f * __expf(a64[1]);
    float Aq64II = 0.25f * __expf(a64[4]);
    float A64dm  = __expf(a64[5]);

    // Emission LUT (conflict-free LDS.128): epb[sym*16+h] = exp(e[4h..4h+3][sym])
    const float4* e4 = (const float4*)(e + (size_t)b * K * 4);
    float4 e0 = e4[k0], e1 = e4[k0 + 1], e2 = e4[k0 + 2], e3 = e4[k0 + 3];
    float4* epb = sh_e + (size_t)((wIn * 2 + half) * 4) * 16;
    epb[0 * 16 + h] = make_float4(__expf(e0.x), __expf(e1.x), __expf(e2.x), __expf(e3.x));
    epb[1 * 16 + h] = make_float4(__expf(e0.y), __expf(e1.y), __expf(e2.y), __expf(e3.y));
    epb[2 * 16 + h] = make_float4(__expf(e0.z), __expf(e1.z), __expf(e2.z), __expf(e3.z));
    epb[3 * 16 + h] = make_float4(__expf(e0.w), __expf(e1.w), __expf(e2.w), __expf(e3.w));
    const char* epbh = (const char*)epb + h * 16;

    // Symbols to shared, pre-scaled by 256 (LUT byte offset), padded 16
    // front/back so the skewed prefetch never clamps.
    const int4* x4 = (const int4*)(x + (size_t)b * L);
    int* xr = sh_x + (wIn * 2 + half) * 160;
    {
        int4 xa = x4[h], xb = x4[h + 16];
        xr[h] = 0; xr[144 + h] = 0;
        xr[16 + 4 * h + 0] = xa.x << 8;
        xr[16 + 4 * h + 1] = xa.y << 8;
        xr[16 + 4 * h + 2] = xa.z << 8;
        xr[16 + 4 * h + 3] = xa.w << 8;
        xr[80 + 4 * h + 0] = xb.x << 8;
        xr[80 + 4 * h + 1] = xb.y << 8;
        xr[80 + 4 * h + 2] = xb.z << 8;
        xr[80 + 4 * h + 3] = xb.w << 8;
    }
    const int* rawp = xr + 17 - h;   // rawp[w] = x[w - h + 1] << 8

    // Flowing init: lane 0 preset; all other lanes exactly zero.
    float FM0 = (h == 0) ? 1.0f : 0.0f;
    float FM1 = 0.0f, FM2 = 0.0f, FM3 = 0.0f;
    float SI0 = 0.0f, SI1 = 0.0f, SI2 = 0.0f, SI3 = 0.0f;
    float SI64 = 0.0f;
    float v3x = 0.0f;                 // export fM'[4h+4] / fM[64] shadow
    float FD0 = 0.0f, FD1 = 0.0f, FD2 = 0.0f, FD3 = 0.0f;
    float fd4x = 0.0f;                // export fD'[4h+4] / fD[64] shadow
    if (h == 0) {
        FD1 = Amd0;                   // fDinit[1] = Amd[0] * fM0[0]
        FD2 = Add1 * FD1;             // fDinit[2]
        FD3 = Add2 * FD2;             // fDinit[3]
        fd4x = Add3 * FD3;            // export fDinit[4] for lane 1's init step
    }
    int Ex = 0;
    float af = (h == 0) ? 0.0f : 1.0f;

    __syncthreads();                  // shared LUTs + symbols visible

    int nsymB = (h == 0) ? xr[16] : 0;   // symbol for lane's w=0 step (pad for h>0)

    // ── uniform, guard-free loop: w = 0..142; rescale heads at w ≡ 3 (mod 4)
    ITER(0, false);
    ITER(1, false);
    ITER(2, false);
    #pragma unroll 1
    for (int wb = 3; wb < 143; wb += 4) {
        ITER(wb,     true);
        ITER(wb + 1, false);
        ITER(wb + 2, false);
        ITER(wb + 3, false);
    }

    // KLD: each hlane handles one latent dim for its batch.
    float kt;
    {
        float mu = mus[(size_t)b * E_DIM + h];
        float lv = lvs[(size_t)b * E_DIM + h];
        kt = 1.0f + lv - mu * mu - __expf(lv);
    }
    kt += __shfl_xor_sync(FULL, kt, 8, 16);
    kt += __shfl_xor_sync(FULL, kt, 4, 16);
    kt += __shfl_xor_sync(FULL, kt, 2, 16);
    kt += __shfl_xor_sync(FULL, kt, 1, 16);
    float kld = -0.5f * kt;

    if (h == 15) {
        // Lane 15's step 127 committed at w = 142:
        // fM[64]=v3x, A64im*fI[64]=SI64, fD[64]=fd4x at scale 2^Ex.
        float fin = fmaf(A64mm, v3x, fmaf(A64dm, fd4x, SI64));
        g_loss[b] = -(logf(fin) + (float)Ex * 0.69314718055994531f) + kld;
    }

    // ── Fused deterministic final reduction (last-block-done) ──
    __threadfence();
    __syncthreads();
    if (threadIdx.x == 0) s_rank = atomicAdd(&g_ctr, 1);
    __syncthreads();
    if (s_rank == gridDim.x - 1) {
        __threadfence();
        float v = 0.0f;
        #pragma unroll
        for (int i = 0; i < B / 64; ++i)
            v += __ldcg(&g_loss[threadIdx.x + i * 64]);
        v += __shfl_xor_sync(FULL, v, 16);
        v += __shfl_xor_sync(FULL, v, 8);
        v += __shfl_xor_sync(FULL, v, 4);
        v += __shfl_xor_sync(FULL, v, 2);
        v += __shfl_xor_sync(FULL, v, 1);
        if (lane == 0) sw[wIn] = v;
        __syncthreads();
        if (threadIdx.x == 0) {
            out[0] = (sw[0] + sw[1]) * (1.0f / (float)B);
            g_ctr = 0;   // reset for next graph replay
        }
    }
}

extern "C" void kernel_launch(void* const* d_in, const int* in_sizes, int n_in,
                              void* d_out, int out_size)
{
    const int*   x   = (const int*)d_in[0];
    const float* a   = (const float*)d_in[1];
    const float* e   = (const float*)d_in[2];
    const float* mus = (const float*)d_in[3];
    const float* lvs = (const float*)d_in[4];

    // 1024 blocks × 2 warps × 2 batches/warp = 4096 batch elements.
    phmm_kernel<<<B / 4, 64>>>(x, a, e, mus, lvs, (float*)d_out);
}

// round 15
// speedup vs baseline: 1.1750x; 1.1587x over previous
#include <cuda_runtime.h>

#define FULL 0xffffffffu

constexpr int B = 4096;
constexpr int K = 64;
constexpr int L = 128;
constexpr int E_DIM = 16;

__device__ float g_loss[B];
__device__ unsigned g_ctr = 0;

// Wavefront-pipelined pHMM forward with flowing initialization and
// SOFTWARE-PIPELINED IMPORTS.
// Two batch elements per warp (16-lane halves). Lane h owns states
// {4h..4h+3}; lane 15 shadows state 64. At wall-iteration w lane h processes
// step l = w - h, consuming lane h-1's same-step exports (v3 = fM'[4h],
// fd4 = fD'[4h]) produced at iteration w-1. No ramp guards: all-zero state
// is an exact fixpoint; lane 0 is preset and the wavefront constructs each
// lane's init in flight.
//
// Import pipelining: the two cross-lane shuffles and the emission LDS.128
// for iteration w+1 are issued at the END of iteration w (right after the
// exports commit), so their latency overlaps iteration w+1's independent
// q/nI front (which reads only committed per-lane state). At rescale heads
// the imports are shuffled post-rescale and af is refreshed from post-commit
// Ex at the same point — semantics identical to head-of-loop shuffles.
//
// SI fold: insert state stored pre-multiplied, SI_k = Aim_k * fI_k, so
// q_k = Amm*FM + Adm*FD + SI. SI'_k = P_k*FM_k + AqII_k*SI_k with
// P_k = Aim_k * 0.25 * exp(M2I), AqII_k = 0.25 * exp(I2I). State 64:
// SI64 = A64im * fI64; the final sum uses SI64 directly.
//
// Per-lane power-of-2 exponent Ex; alignment factor af = 2^(E_{h-1}-E_h) is
// piecewise-constant between rescale heads ((w & 3) == 3), refreshed there;
// af = 0 on lane 0 absorbs the k=0 boundary. The rescale max includes the
// SI values (SI has a self-loop with AqII possibly > 1 — R11 failure mode).
// Idle (all-zero) lanes force exv = 0.
// Export shortcut: fd4 = segB*fd0 + (c0*u0 + c1*u1 + c2*u2 + u3).
// Transitions order: M2M,M2I,M2D,I2M,I2I,D2M,D2D.

#define ITER(WV, RESC) do {                                                    \
    /* imports pv3in/pfdin/evcur were prefetched by the previous iteration */  \
    float pv3a = pv3in * af;                                                   \
    float pfda = pfdin * af;                                                   \
    float q0 = fmaf(Amm0, FM0, fmaf(Adm0, FD0, SI0));                          \
    float q1 = fmaf(Amm1, FM1, fmaf(Adm1, FD1, SI1));                          \
    float q2 = fmaf(Amm2, FM2, fmaf(Adm2, FD2, SI2));                          \
    float q3 = fmaf(Amm3, FM3, fmaf(Adm3, FD3, SI3));                          \
    float nI0 = fmaf(P0, FM0, AqII0 * SI0);                                    \
    float nI1 = fmaf(P1, FM1, AqII1 * SI1);                                    \
    float nI2 = fmaf(P2, FM2, AqII2 * SI2);                                    \
    float nI3 = fmaf(P3, FM3, AqII3 * SI3);                                    \
    float nSI64 = fmaf(P64, v3x, Aq64II * SI64);                               \
    float v0 = evcur.x * q0, v1 = evcur.y * q1, v2 = evcur.z * q2;             \
    float nv3 = evcur.w * q3;                                                  \
    float u0 = Amd0 * pv3a, u1 = Amd1 * v0, u2 = Amd2 * v1, u3 = Amd3 * v2;    \
    float t1 = fmaf(c2, u2, u3);                                               \
    float t2 = fmaf(c1, u1, t1);                                               \
    float alpha = fmaf(c0, u0, t2);                                            \
    float fd0 = pfda;                                                          \
    float nfd4 = fmaf(segB, fd0, alpha);     /* export: 1 FMA off import */    \
    float fd1 = fmaf(Add0, fd0, u0);                                           \
    float fd2 = fmaf(Add1, fd1, u1);                                           \
    float fd3 = fmaf(Add2, fd2, u2);                                           \
    float nM0 = pv3a, nM1 = v0, nM2 = v1, nM3 = v2;                            \
    int exv = 0;                                                               \
    if (RESC) {                                                                \
        float m = fmaxf(fmaxf(nM0, nM1), fmaxf(nM2, nM3));                     \
        m = fmaxf(m, fmaxf(fmaxf(nI0, nI1), fmaxf(nI2, nI3)));                 \
        m = fmaxf(m, fmaxf(fmaxf(fd0, fd1), fmaxf(fd2, fd3)));                 \
        m = fmaxf(m, fmaxf(nv3, fmaxf(nfd4, nSI64)));                          \
        exv = (int)((__float_as_uint(m) >> 23) & 255) - 127;                   \
        exv = (m > 0.0f) ? exv : 0;          /* idle lanes: no-op rescale */   \
        float sc = __uint_as_float((unsigned)(127 - exv) << 23);               \
        nM0 *= sc; nM1 *= sc; nM2 *= sc; nM3 *= sc;                            \
        nI0 *= sc; nI1 *= sc; nI2 *= sc; nI3 *= sc;                            \
        fd0 *= sc; fd1 *= sc; fd2 *= sc; fd3 *= sc;                            \
        nv3 *= sc; nfd4 *= sc; nSI64 *= sc;                                    \
    }                                                                          \
    FM0 = nM0; FM1 = nM1; FM2 = nM2; FM3 = nM3;                                \
    SI0 = nI0; SI1 = nI1; SI2 = nI2; SI3 = nI3;                                \
    FD0 = fd0; FD1 = fd1; FD2 = fd2; FD3 = fd3;                                \
    SI64 = nSI64; v3x = nv3; fd4x = nfd4; Ex += exv;                           \
    if (RESC) {   /* refresh alignment factor (valid until next head) */       \
        int pE = __shfl_up_sync(FULL, Ex, 1, 16);                              \
        int dE = pE - Ex; dE = max(-126, min(126, dE));                        \
        af = (h == 0) ? 0.0f                                                   \
                      : __uint_as_float((unsigned)(127 + dE) << 23);           \
    }                                                                          \
    /* prefetch imports + emission row for iteration WV+1 */                   \
    pv3in = __shfl_up_sync(FULL, v3x, 1, 16);                                  \
    pfdin = __shfl_up_sync(FULL, fd4x, 1, 16);                                 \
    evcur = *(const float4*)(epbh + rawp[WV]);  /* symbol of step WV+1-h */    \
} while (0)

__global__ __launch_bounds__(64) void phmm_kernel(
    const int*   __restrict__ x,
    const float* __restrict__ a,
    const float* __restrict__ e,
    const float* __restrict__ mus,
    const float* __restrict__ lvs,
    float*       __restrict__ out)
{
    const int lane = threadIdx.x & 31;
    const int half = lane >> 4;
    const int h    = lane & 15;
    const int wIn  = threadIdx.x >> 5;
    const int warp = blockIdx.x * 2 + wIn;
    const int b = 2 * warp + half;

    __shared__ float4 sh_e[2 * 2 * 4 * 16];  // [warp][half][symbol][hlane]
    __shared__ int    sh_x[2 * 2 * 160];     // padded symbols (×256 pre-scaled)
    __shared__ float sw[2];
    __shared__ unsigned s_rank;

    const float* ab = a + (size_t)b * (K + 1) * 7;
    const int k0 = 4 * h;
    const float* A0 = ab + (k0 + 0) * 7;
    const float* A1 = ab + (k0 + 1) * 7;
    const float* A2 = ab + (k0 + 2) * 7;
    const float* A3 = ab + (k0 + 3) * 7;

    float Amm0 = __expf(A0[0]), Amm1 = __expf(A1[0]);
    float Amm2 = __expf(A2[0]), Amm3 = __expf(A3[0]);
    float Amd0 = __expf(A0[2]), Amd1 = __expf(A1[2]);
    float Amd2 = __expf(A2[2]), Amd3 = __expf(A3[2]);
    float Aim0 = __expf(A0[3]), Aim1 = __expf(A1[3]);
    float Aim2 = __expf(A2[3]), Aim3 = __expf(A3[3]);
    // SI-fold coefficients: P = Aim * (0.25 * exp(M2I)), AqII = 0.25 * exp(I2I)
    float P0 = Aim0 * 0.25f * __expf(A0[1]), P1 = Aim1 * 0.25f * __expf(A1[1]);
    float P2 = Aim2 * 0.25f * __expf(A2[1]), P3 = Aim3 * 0.25f * __expf(A3[1]);
    float AqII0 = 0.25f * __expf(A0[4]), AqII1 = 0.25f * __expf(A1[4]);
    float AqII2 = 0.25f * __expf(A2[4]), AqII3 = 0.25f * __expf(A3[4]);
    float Adm0 = __expf(A0[5]), Adm1 = __expf(A1[5]);
    float Adm2 = __expf(A2[5]), Adm3 = __expf(A3[5]);
    float Add0 = __expf(A0[6]), Add1 = __expf(A1[6]);
    float Add2 = __expf(A2[6]), Add3 = __expf(A3[6]);

    // Export/alpha coefficients: fd4 = segB*fd0 + c0*u0 + c1*u1 + c2*u2 + u3
    float c2 = Add3;
    float c1 = Add3 * Add2;
    float c0 = c1 * Add1;
    float segB = c0 * Add0;

    const float* a64 = ab + K * 7;
    float A64mm  = __expf(a64[0]);
    float A64im  = __expf(a64[3]);
    float P64    = A64im * 0.25f * __expf(a64[1]);
    float Aq64II = 0.25f * __expf(a64[4]);
    float A64dm  = __expf(a64[5]);

    // Emission LUT (conflict-free LDS.128): epb[sym*16+h] = exp(e[4h..4h+3][sym])
    const float4* e4 = (const float4*)(e + (size_t)b * K * 4);
    float4 e0 = e4[k0], e1 = e4[k0 + 1], e2 = e4[k0 + 2], e3 = e4[k0 + 3];
    float4* epb = sh_e + (size_t)((wIn * 2 + half) * 4) * 16;
    epb[0 * 16 + h] = make_float4(__expf(e0.x), __expf(e1.x), __expf(e2.x), __expf(e3.x));
    epb[1 * 16 + h] = make_float4(__expf(e0.y), __expf(e1.y), __expf(e2.y), __expf(e3.y));
    epb[2 * 16 + h] = make_float4(__expf(e0.z), __expf(e1.z), __expf(e2.z), __expf(e3.z));
    epb[3 * 16 + h] = make_float4(__expf(e0.w), __expf(e1.w), __expf(e2.w), __expf(e3.w));
    const char* epbh = (const char*)epb + h * 16;

    // Symbols to shared, pre-scaled by 256 (LUT byte offset), padded 16
    // front/back so the skewed prefetch never clamps.
    const int4* x4 = (const int4*)(x + (size_t)b * L);
    int* xr = sh_x + (wIn * 2 + half) * 160;
    {
        int4 xa = x4[h], xb = x4[h + 16];
        xr[h] = 0; xr[144 + h] = 0;
        xr[16 + 4 * h + 0] = xa.x << 8;
        xr[16 + 4 * h + 1] = xa.y << 8;
        xr[16 + 4 * h + 2] = xa.z << 8;
        xr[16 + 4 * h + 3] = xa.w << 8;
        xr[80 + 4 * h + 0] = xb.x << 8;
        xr[80 + 4 * h + 1] = xb.y << 8;
        xr[80 + 4 * h + 2] = xb.z << 8;
        xr[80 + 4 * h + 3] = xb.w << 8;
    }
    const int* rawp = xr + 17 - h;   // rawp[w] = x[w - h + 1] << 8

    // Flowing init: lane 0 preset; all other lanes exactly zero.
    float FM0 = (h == 0) ? 1.0f : 0.0f;
    float FM1 = 0.0f, FM2 = 0.0f, FM3 = 0.0f;
    float SI0 = 0.0f, SI1 = 0.0f, SI2 = 0.0f, SI3 = 0.0f;
    float SI64 = 0.0f;
    float v3x = 0.0f;                 // export fM'[4h+4] / fM[64] shadow
    float FD0 = 0.0f, FD1 = 0.0f, FD2 = 0.0f, FD3 = 0.0f;
    float fd4x = 0.0f;                // export fD'[4h+4] / fD[64] shadow
    if (h == 0) {
        FD1 = Amd0;                   // fDinit[1] = Amd[0] * fM0[0]
        FD2 = Add1 * FD1;             // fDinit[2]
        FD3 = Add2 * FD2;             // fDinit[3]
        fd4x = Add3 * FD3;            // export fDinit[4] for lane 1's init step
    }
    int Ex = 0;
    float af = (h == 0) ? 0.0f : 1.0f;

    __syncthreads();                  // shared LUTs + symbols visible

    // Prologue prefetch for iteration 0.
    float pv3in = __shfl_up_sync(FULL, v3x, 1, 16);
    float pfdin = __shfl_up_sync(FULL, fd4x, 1, 16);
    float4 evcur = *(const float4*)(epbh + ((h == 0) ? xr[16] : 0));

    // ── uniform, guard-free loop: w = 0..142; rescale heads at w ≡ 3 (mod 4)
    ITER(0, false);
    ITER(1, false);
    ITER(2, false);
    #pragma unroll 1
    for (int wb = 3; wb < 143; wb += 4) {
        ITER(wb,     true);
        ITER(wb + 1, false);
        ITER(wb + 2, false);
        ITER(wb + 3, false);
    }

    // KLD: each hlane handles one latent dim for its batch.
    float kt;
    {
        float mu = mus[(size_t)b * E_DIM + h];
        float lv = lvs[(size_t)b * E_DIM + h];
        kt = 1.0f + lv - mu * mu - __expf(lv);
    }
    kt += __shfl_xor_sync(FULL, kt, 8, 16);
    kt += __shfl_xor_sync(FULL, kt, 4, 16);
    kt += __shfl_xor_sync(FULL, kt, 2, 16);
    kt += __shfl_xor_sync(FULL, kt, 1, 16);
    float kld = -0.5f * kt;

    if (h == 15) {
        // Lane 15's step 127 committed at w = 142:
        // fM[64]=v3x, A64im*fI[64]=SI64, fD[64]=fd4x at scale 2^Ex.
        float fin = fmaf(A64mm, v3x, fmaf(A64dm, fd4x, SI64));
        g_loss[b] = -(logf(fin) + (float)Ex * 0.69314718055994531f) + kld;
    }

    // ── Fused deterministic final reduction (last-block-done) ──
    __threadfence();
    __syncthreads();
    if (threadIdx.x == 0) s_rank = atomicAdd(&g_ctr, 1);
    __syncthreads();
    if (s_rank == gridDim.x - 1) {
        __threadfence();
        float v = 0.0f;
        #pragma unroll
        for (int i = 0; i < B / 64; ++i)
            v += __ldcg(&g_loss[threadIdx.x + i * 64]);
        v += __shfl_xor_sync(FULL, v, 16);
        v += __shfl_xor_sync(FULL, v, 8);
        v += __shfl_xor_sync(FULL, v, 4);
        v += __shfl_xor_sync(FULL, v, 2);
        v += __shfl_xor_sync(FULL, v, 1);
        if (lane == 0) sw[wIn] = v;
        __syncthreads();
        if (threadIdx.x == 0) {
            out[0] = (sw[0] + sw[1]) * (1.0f / (float)B);
            g_ctr = 0;   // reset for next graph replay
        }
    }
}

extern "C" void kernel_launch(void* const* d_in, const int* in_sizes, int n_in,
                              void* d_out, int out_size)
{
    const int*   x   = (const int*)d_in[0];
    const float* a   = (const float*)d_in[1];
    const float* e   = (const float*)d_in[2];
    const float* mus = (const float*)d_in[3];
    const float* lvs = (const float*)d_in[4];

    // 1024 blocks × 2 warps × 2 batches/warp = 4096 batch elements.
    phmm_kernel<<<B / 4, 64>>>(x, a, e, mus, lvs, (float*)d_out);
}